// round 13
// baseline (speedup 1.0000x reference)
#include <cuda_runtime.h>
#include <cuda_bf16.h>

// Zim_67430986547716 — bbox mask + Gaussian point mask.
// R13: hybrid of measured-best parts.
//  - Main loop, table layout, epilogue, launch shape: R8 VERBATIM (the
//    highest measured issue-efficiency config: 59.6%, kernel 7.58us).
//  - Prologue only: R12-style. Thread (p=tid&31, g=tid>>5) loads point p once
//    (coalesced float2, 8-way L1 broadcast) and writes its share of R8's
//    tables: 2 dx-pair words + 4 dy words. ~75 fewer slots/thread, one LDG
//    chain instead of ten.
// Tropical trick: max_p exp(-d2/882) = exp(-(min_p d2)/882); invalid points
// carry +30000 bias (exp -> exactly 0). All sums < 65535 (u16-safe).

#define MASK_N 64
#define NPTS   32
#define INV_STRIDE (1.0f / 16.0f)
#define INV_2SIG2  (1.0f / 882.0f)   // 2*21*21

__global__ __launch_bounds__(256, 8)
void zim_masks_kernel(const float* __restrict__ boxes,
                      const float* __restrict__ pts,
                      float* __restrict__ bbox_out,
                      float* __restrict__ point_out)
{
    __shared__ unsigned int sdx2p[NPTS * 16];  // 2KB: [p][cpair] = dx2(2c)|dx2(2c+1)<<16
    __shared__ unsigned int sdy2d[NPTS * 32];  // 4KB: [p][row]   = (dy2+bias) duplicated

    const int b      = blockIdx.x;
    const int quad   = blockIdx.y;              // 0..3
    const int i_base = (quad >> 1) << 5;        // 0 or 32
    const int j_base = (quad & 1) << 5;         // 0 or 32
    const int tid    = threadIdx.x;

    // ---- bbox bounds: one LDG.128, uniform ----
    const float4 bx = __ldg(&reinterpret_cast<const float4*>(boxes)[b]);
    const int xmin_i = max((int)floorf(fminf(bx.x, bx.z) * INV_STRIDE), 0);
    const int ymin_i = max((int)floorf(fminf(bx.y, bx.w) * INV_STRIDE), 0);
    const int xmax_i = min((int)floorf(fmaxf(bx.x, bx.z) * INV_STRIDE) + 1, MASK_N);
    const int ymax_i = min((int)floorf(fmaxf(bx.y, bx.w) * INV_STRIDE) + 1, MASK_N);

    // ---- prologue: thread (p, g) loads point p once, writes its table share ----
    {
        const int p = tid & 31;                 // point index
        const int g = tid >> 5;                 // group 0..7
        const float2 xy = __ldg(&reinterpret_cast<const float2*>(pts)[b * NPTS + p]);
        const int px = (int)floorf(xy.x * INV_STRIDE);
        const int py = (int)floorf(xy.y * INV_STRIDE);
        const bool valid = (px >= 0) & (py >= 0) & (px < MASK_N) & (py < MASK_N);
        const int bias = valid ? 0 : 30000;

        // dx pairs: this quadrant's col-pairs 2g and 2g+1 (cols 4g..4g+3)
        const int d0 = j_base + (g << 2) - px;
        const int d1 = d0 + 1, d2 = d0 + 2, d3 = d0 + 3;
        sdx2p[p * 16 + (g << 1) + 0] =
            (unsigned int)(d0 * d0) | ((unsigned int)(d1 * d1) << 16);
        sdx2p[p * 16 + (g << 1) + 1] =
            (unsigned int)(d2 * d2) | ((unsigned int)(d3 * d3) << 16);

        // dy duplicated: this quadrant's rows 4g..4g+3
        #pragma unroll
        for (int r = 0; r < 4; r++) {
            const int row = (g << 2) + r;
            const int d = i_base + row - py;
            const unsigned int v = (unsigned int)(d * d + bias);
            sdy2d[p * 32 + row] = v | (v << 16);
        }
    }
    __syncthreads();

    // ---- per-thread: 1 row x 4 cols of the quadrant, u16x2 SIMD min (R8) ----
    const int il = tid >> 3;            // 0..31 local row
    const int cg = (tid & 7);           // col group: cols 4*cg .. 4*cg+3

    unsigned int m01 = 0xFFFFFFFFu, m23 = 0xFFFFFFFFu;

    const unsigned int* dyp = &sdy2d[il];
    const unsigned int* dxp = &sdx2p[cg * 2];

    #pragma unroll 8
    for (int p = 0; p < NPTS; p++) {
        const unsigned int dyd = dyp[p * 32];
        const uint2 dx = *reinterpret_cast<const uint2*>(dxp + p * 16);
        m01 = __viaddmin_u16x2(dyd, dx.x, m01);
        m23 = __viaddmin_u16x2(dyd, dx.y, m23);
    }

    // ---- unpack + one exp per pixel ----
    const float g0 = __expf((float)(m01 & 0xFFFFu) * -INV_2SIG2);
    const float g1 = __expf((float)(m01 >> 16)     * -INV_2SIG2);
    const float g2 = __expf((float)(m23 & 0xFFFFu) * -INV_2SIG2);
    const float g3 = __expf((float)(m23 >> 16)     * -INV_2SIG2);

    // ---- stores ----
    const int i = i_base + il;
    const int j = j_base + (cg << 2);
    const size_t base = (size_t)b * (MASK_N * MASK_N) + (size_t)i * MASK_N + j;

    *reinterpret_cast<float4*>(point_out + base) = make_float4(g0, g1, g2, g3);

    const bool inY = (i >= ymin_i) & (i < ymax_i);
    float4 bv;
    bv.x = (inY & (j + 0 >= xmin_i) & (j + 0 < xmax_i)) ? 1.f : 0.f;
    bv.y = (inY & (j + 1 >= xmin_i) & (j + 1 < xmax_i)) ? 1.f : 0.f;
    bv.z = (inY & (j + 2 >= xmin_i) & (j + 2 < xmax_i)) ? 1.f : 0.f;
    bv.w = (inY & (j + 3 >= xmin_i) & (j + 3 < xmax_i)) ? 1.f : 0.f;
    *reinterpret_cast<float4*>(bbox_out + base) = bv;
}

extern "C" void kernel_launch(void* const* d_in, const int* in_sizes, int n_in,
                              void* d_out, int out_size) {
    const float* boxes = (const float*)d_in[0];   // 256*4
    const float* pts   = (const float*)d_in[1];   // 256*32*2
    float* out = (float*)d_out;                   // 2 * 256*64*64
    const int B = in_sizes[0] / 4;                // 256
    float* bbox_out  = out;
    float* point_out = out + (size_t)B * MASK_N * MASK_N;
    dim3 grid(B, 4);
    zim_masks_kernel<<<grid, 256>>>(boxes, pts, bbox_out, point_out);
}

// round 14
// speedup vs baseline: 1.1433x; 1.1433x over previous
#include <cuda_runtime.h>
#include <cuda_bf16.h>

// Zim_67430986547716 — bbox mask + Gaussian point mask.
// R14: R8 verbatim (main loop / tables / epilogue / 1024x256 single-wave
// shape — the measured 59.6%-issue config) + conflict-free vectorized
// prologue. R13's prologue had 32-way STS bank conflicts (lane stride 32
// words); here thread (p=tid>>3, s=tid&7) writes CONTIGUOUS addresses:
//   dy: one uint4 STS.128 at sdy2d[p*32 + 4s]  (rows 4s..4s+3)
//   dx: one uint2 STS.64  at sdx2p[p*16 + 2s]  (cols 4s..4s+3)
// One broadcast LDG.64 per thread. Tropical trick unchanged.

#define MASK_N 64
#define NPTS   32
#define INV_STRIDE (1.0f / 16.0f)
#define INV_2SIG2  (1.0f / 882.0f)   // 2*21*21

__global__ __launch_bounds__(256, 8)
void zim_masks_kernel(const float* __restrict__ boxes,
                      const float* __restrict__ pts,
                      float* __restrict__ bbox_out,
                      float* __restrict__ point_out)
{
    __shared__ __align__(16) unsigned int sdx2p[NPTS * 16]; // 2KB: [p][cpair] dx2 u16 pairs
    __shared__ __align__(16) unsigned int sdy2d[NPTS * 32]; // 4KB: [p][row] (dy2+bias) dup

    const int b      = blockIdx.x;
    const int quad   = blockIdx.y;              // 0..3
    const int i_base = (quad >> 1) << 5;        // 0 or 32
    const int j_base = (quad & 1) << 5;         // 0 or 32
    const int tid    = threadIdx.x;

    // ---- bbox bounds: one LDG.128, uniform ----
    const float4 bx = __ldg(&reinterpret_cast<const float4*>(boxes)[b]);
    const int xmin_i = max((int)floorf(fminf(bx.x, bx.z) * INV_STRIDE), 0);
    const int ymin_i = max((int)floorf(fminf(bx.y, bx.w) * INV_STRIDE), 0);
    const int xmax_i = min((int)floorf(fmaxf(bx.x, bx.z) * INV_STRIDE) + 1, MASK_N);
    const int ymax_i = min((int)floorf(fmaxf(bx.y, bx.w) * INV_STRIDE) + 1, MASK_N);

    // ---- prologue: thread (p = tid>>3, s = tid&7), contiguous STS ----
    {
        const int p = tid >> 3;                 // point index (4 lanes share)
        const int s = tid & 7;                  // segment 0..7
        const float2 xy = __ldg(&reinterpret_cast<const float2*>(pts)[b * NPTS + p]);
        const int px = (int)floorf(xy.x * INV_STRIDE);
        const int py = (int)floorf(xy.y * INV_STRIDE);
        const bool valid = (px >= 0) & (py >= 0) & (px < MASK_N) & (py < MASK_N);
        const int bias = valid ? 0 : 30000;

        // dx: cols 4s..4s+3 of this quadrant -> 2 packed pairs, one STS.64
        const int d0 = j_base + (s << 2) - px;
        const int d1 = d0 + 1, d2 = d0 + 2, d3 = d0 + 3;
        const uint2 dxw = make_uint2(
            (unsigned int)(d0 * d0) | ((unsigned int)(d1 * d1) << 16),
            (unsigned int)(d2 * d2) | ((unsigned int)(d3 * d3) << 16));
        *reinterpret_cast<uint2*>(&sdx2p[p * 16 + (s << 1)]) = dxw;

        // dy: rows 4s..4s+3 duplicated -> one STS.128
        const int e0 = i_base + (s << 2) - py;
        const int e1 = e0 + 1, e2 = e0 + 2, e3 = e0 + 3;
        const unsigned int v0 = (unsigned int)(e0 * e0 + bias);
        const unsigned int v1 = (unsigned int)(e1 * e1 + bias);
        const unsigned int v2 = (unsigned int)(e2 * e2 + bias);
        const unsigned int v3 = (unsigned int)(e3 * e3 + bias);
        const uint4 dyw = make_uint4(v0 | (v0 << 16), v1 | (v1 << 16),
                                     v2 | (v2 << 16), v3 | (v3 << 16));
        *reinterpret_cast<uint4*>(&sdy2d[p * 32 + (s << 2)]) = dyw;
    }
    __syncthreads();

    // ---- per-thread: 1 row x 4 cols of the quadrant, u16x2 SIMD min (R8) ----
    const int il = tid >> 3;            // 0..31 local row
    const int cg = (tid & 7);           // col group: cols 4*cg .. 4*cg+3

    unsigned int m01 = 0xFFFFFFFFu, m23 = 0xFFFFFFFFu;

    const unsigned int* dyp = &sdy2d[il];
    const unsigned int* dxp = &sdx2p[cg * 2];

    #pragma unroll 8
    for (int p = 0; p < NPTS; p++) {
        const unsigned int dyd = dyp[p * 32];
        const uint2 dx = *reinterpret_cast<const uint2*>(dxp + p * 16);
        m01 = __viaddmin_u16x2(dyd, dx.x, m01);
        m23 = __viaddmin_u16x2(dyd, dx.y, m23);
    }

    // ---- unpack + one exp per pixel ----
    const float g0 = __expf((float)(m01 & 0xFFFFu) * -INV_2SIG2);
    const float g1 = __expf((float)(m01 >> 16)     * -INV_2SIG2);
    const float g2 = __expf((float)(m23 & 0xFFFFu) * -INV_2SIG2);
    const float g3 = __expf((float)(m23 >> 16)     * -INV_2SIG2);

    // ---- stores ----
    const int i = i_base + il;
    const int j = j_base + (cg << 2);
    const size_t base = (size_t)b * (MASK_N * MASK_N) + (size_t)i * MASK_N + j;

    *reinterpret_cast<float4*>(point_out + base) = make_float4(g0, g1, g2, g3);

    const bool inY = (i >= ymin_i) & (i < ymax_i);
    float4 bv;
    bv.x = (inY & (j + 0 >= xmin_i) & (j + 0 < xmax_i)) ? 1.f : 0.f;
    bv.y = (inY & (j + 1 >= xmin_i) & (j + 1 < xmax_i)) ? 1.f : 0.f;
    bv.z = (inY & (j + 2 >= xmin_i) & (j + 2 < xmax_i)) ? 1.f : 0.f;
    bv.w = (inY & (j + 3 >= xmin_i) & (j + 3 < xmax_i)) ? 1.f : 0.f;
    *reinterpret_cast<float4*>(bbox_out + base) = bv;
}

extern "C" void kernel_launch(void* const* d_in, const int* in_sizes, int n_in,
                              void* d_out, int out_size) {
    const float* boxes = (const float*)d_in[0];   // 256*4
    const float* pts   = (const float*)d_in[1];   // 256*32*2
    float* out = (float*)d_out;                   // 2 * 256*64*64
    const int B = in_sizes[0] / 4;                // 256
    float* bbox_out  = out;
    float* point_out = out + (size_t)B * MASK_N * MASK_N;
    dim3 grid(B, 4);
    zim_masks_kernel<<<grid, 256>>>(boxes, pts, bbox_out, point_out);
}

// round 15
// speedup vs baseline: 1.2362x; 1.0812x over previous
#include <cuda_runtime.h>
#include <cuda_bf16.h>

// Zim_67430986547716 — bbox mask + Gaussian point mask.
// R15: halve main-loop LDS instructions by fetching TWO points per load.
//  - sdy[row][p] (pad-36):  uint2 @ even p = dup-dy words of points p, p+1
//  - sdx[cg][p]  (pad-34 uint2, 16B aligned): uint4 = both points' dx pairs
//  - per 2 points: 2 LDS + 4 VIADDMNMX (was 4 LDS + 4V). Main 128->96 slots,
//    LDS instr 64->32 (per-SMSP LDS floor halves).
// Shape: 1024 quadrant blocks x 256 thr, single wave (launch_bounds 256,8).
// Tropical trick: max_p exp(-d2/882) = exp(-(min_p d2)/882); invalid bias
// +30000 (exp -> exactly 0). Inputs give px,py in [0,63] so sums fit u16.

#define MASK_N 64
#define NPTS   32
#define INV_STRIDE (1.0f / 16.0f)
#define INV_2SIG2  (1.0f / 882.0f)   // 2*21*21

#define DY_STRIDE 36   // uints per row (pad 4)
#define DX_STRIDE 34   // uint2 per col-group (pad 2, even => 16B-aligned pairs)

__global__ __launch_bounds__(256, 8)
void zim_masks_kernel(const float* __restrict__ boxes,
                      const float* __restrict__ pts,
                      float* __restrict__ bbox_out,
                      float* __restrict__ point_out)
{
    __shared__ __align__(16) unsigned int sdy[32 * DY_STRIDE]; // [row][p] dup (dy2+bias)
    __shared__ __align__(16) uint2        sdx[8 * DX_STRIDE];  // [cg][p] dx2 pairs (4 cols)

    const int b      = blockIdx.x;
    const int quad   = blockIdx.y;              // 0..3
    const int i_base = (quad >> 1) << 5;        // 0 or 32
    const int j_base = (quad & 1) << 5;         // 0 or 32
    const int tid    = threadIdx.x;

    // ---- bbox bounds: one LDG.128, uniform ----
    const float4 bx = __ldg(&reinterpret_cast<const float4*>(boxes)[b]);
    const int xmin_i = max((int)floorf(fminf(bx.x, bx.z) * INV_STRIDE), 0);
    const int ymin_i = max((int)floorf(fminf(bx.y, bx.w) * INV_STRIDE), 0);
    const int xmax_i = min((int)floorf(fmaxf(bx.x, bx.z) * INV_STRIDE) + 1, MASK_N);
    const int ymax_i = min((int)floorf(fmaxf(bx.y, bx.w) * INV_STRIDE) + 1, MASK_N);

    // ---- prologue: warp s (=tid>>5), lane = point. Coalesced LDG.64,
    //      conflict-free consecutive STS. ----
    {
        const int s    = tid >> 5;              // 0..7
        const int lane = tid & 31;              // point index
        const float2 xy = __ldg(&reinterpret_cast<const float2*>(pts)[b * NPTS + lane]);
        const int px = (int)floorf(xy.x * INV_STRIDE);
        const int py = (int)floorf(xy.y * INV_STRIDE);
        const bool valid = (px >= 0) & (py >= 0) & (px < MASK_N) & (py < MASK_N);
        const int bias = valid ? 0 : 30000;

        // dx: col group s -> cols j_base+4s .. +3, one uint2 store
        const int d0 = j_base + (s << 2) - px;
        const int d1 = d0 + 1, d2 = d0 + 2, d3 = d0 + 3;
        sdx[s * DX_STRIDE + lane] = make_uint2(
            (unsigned int)(d0 * d0) | ((unsigned int)(d1 * d1) << 16),
            (unsigned int)(d2 * d2) | ((unsigned int)(d3 * d3) << 16));

        // dy: rows 4s..4s+3, duplicated u16x2, consecutive-lane STS.32
        #pragma unroll
        for (int r = 0; r < 4; r++) {
            const int row = (s << 2) + r;
            const int d = i_base + row - py;
            const unsigned int v = (unsigned int)(d * d + bias);
            sdy[row * DY_STRIDE + lane] = v | (v << 16);
        }
    }
    __syncthreads();

    // ---- per-thread: 1 row x 4 cols; 2 points per iteration ----
    const int il = tid >> 3;            // 0..31 local row
    const int cg = tid & 7;             // col group

    unsigned int m01 = 0xFFFFFFFFu, m23 = 0xFFFFFFFFu;

    const unsigned int* dyb = &sdy[il * DY_STRIDE];
    const uint2*        dxb = &sdx[cg * DX_STRIDE];

    #pragma unroll
    for (int p2 = 0; p2 < NPTS / 2; p2++) {
        const uint2 dy = *reinterpret_cast<const uint2*>(dyb + 2 * p2);        // pts 2p2, 2p2+1
        const uint4 dx = *reinterpret_cast<const uint4*>(dxb + 2 * p2);        // both pts' pairs
        m01 = __viaddmin_u16x2(dy.x, dx.x, m01);
        m23 = __viaddmin_u16x2(dy.x, dx.y, m23);
        m01 = __viaddmin_u16x2(dy.y, dx.z, m01);
        m23 = __viaddmin_u16x2(dy.y, dx.w, m23);
    }

    // ---- unpack + one exp per pixel ----
    const float g0 = __expf((float)(m01 & 0xFFFFu) * -INV_2SIG2);
    const float g1 = __expf((float)(m01 >> 16)     * -INV_2SIG2);
    const float g2 = __expf((float)(m23 & 0xFFFFu) * -INV_2SIG2);
    const float g3 = __expf((float)(m23 >> 16)     * -INV_2SIG2);

    // ---- stores ----
    const int i = i_base + il;
    const int j = j_base + (cg << 2);
    const size_t base = (size_t)b * (MASK_N * MASK_N) + (size_t)i * MASK_N + j;

    *reinterpret_cast<float4*>(point_out + base) = make_float4(g0, g1, g2, g3);

    const bool inY = (i >= ymin_i) & (i < ymax_i);
    float4 bv;
    bv.x = (inY & (j + 0 >= xmin_i) & (j + 0 < xmax_i)) ? 1.f : 0.f;
    bv.y = (inY & (j + 1 >= xmin_i) & (j + 1 < xmax_i)) ? 1.f : 0.f;
    bv.z = (inY & (j + 2 >= xmin_i) & (j + 2 < xmax_i)) ? 1.f : 0.f;
    bv.w = (inY & (j + 3 >= xmin_i) & (j + 3 < xmax_i)) ? 1.f : 0.f;
    *reinterpret_cast<float4*>(bbox_out + base) = bv;
}

extern "C" void kernel_launch(void* const* d_in, const int* in_sizes, int n_in,
                              void* d_out, int out_size) {
    const float* boxes = (const float*)d_in[0];   // 256*4
    const float* pts   = (const float*)d_in[1];   // 256*32*2
    float* out = (float*)d_out;                   // 2 * 256*64*64
    const int B = in_sizes[0] / 4;                // 256
    float* bbox_out  = out;
    float* point_out = out + (size_t)B * MASK_N * MASK_N;
    dim3 grid(B, 4);
    zim_masks_kernel<<<grid, 256>>>(boxes, pts, bbox_out, point_out);
}